// round 10
// baseline (speedup 1.0000x reference)
#include <cuda_runtime.h>
#include <math.h>

// Problem shape (fixed): x [T=4, B=32, C=256, H=32, W=32]
#define Tn 4
#define Bn 32
#define Cn 256
#define Pn 1024
#define NSL 1024            // slices = B * 32 pixel-groups (32 pixels each, all channels)
#define NBLK 148            // persistent grid = one CTA per SM (one wave)

// Per-pixel sums: [sel][b][p], sel 0 = csum, 1 = ssq. 256 KB, L2-resident.
__device__ float g_comb[2 * Bn * Pn];
// Per-batch completion counters (self-resetting: finale owner zeroes its batch).
__device__ int g_done[Bn];

__device__ __forceinline__ float4 f4add(float4 a, float4 b) {
    return make_float4(a.x + b.x, a.y + b.y, a.z + b.z, a.w + b.w);
}

// ---------------------------------------------------------------------------
// Fused persistent kernel. Phase 1 is the proven R6 loop, UNTOUCHED.
// After the loop: one fence by the storer threads, one syncthreads, then tid0
// counts each owned slice into its batch's counter. The 32nd increment for a
// batch makes this block that batch's finale owner; finales (box filter +
// cosine collapse + softmax) run at the end, overlapping other blocks'
// remaining phase-1 work. No per-iteration fences, no global barrier.
// ---------------------------------------------------------------------------
__global__ void __launch_bounds__(1024, 1) fused_kernel(const float* __restrict__ xf,
                                                        const int* __restrict__ mask,
                                                        float* __restrict__ out) {
    const float4* __restrict__ X = (const float4*)xf;
    const int tid   = threadIdx.x;
    const int w     = tid >> 5;
    const int l     = tid & 31;
    const int f4    = l & 7;
    const int cbase = w * 8 + (l >> 3) * 2;

    __shared__ float4 scs[32][8];
    __shared__ float4 ssq[32][8];
    __shared__ int s_fin[8];
    __shared__ int s_nfin;

    const size_t tstr = (size_t)Bn * Cn * 256;   // t-plane stride in float4

    int sl = blockIdx.x;
    float4 r[8];
    {
        const int b = sl >> 5, pg = sl & 31;
        const size_t base = ((size_t)b * Cn + cbase) * 256 + pg * 8 + f4;
#pragma unroll
        for (int t = 0; t < 4; ++t) {
            r[t]     = __ldg(X + base + (size_t)t * tstr);
            r[4 + t] = __ldg(X + base + 256 + (size_t)t * tstr);
        }
    }

    for (;;) {
        float4 m0, m1;
        m0.x = (r[0].x + r[1].x + r[2].x + r[3].x) * 0.25f;
        m0.y = (r[0].y + r[1].y + r[2].y + r[3].y) * 0.25f;
        m0.z = (r[0].z + r[1].z + r[2].z + r[3].z) * 0.25f;
        m0.w = (r[0].w + r[1].w + r[2].w + r[3].w) * 0.25f;
        m1.x = (r[4].x + r[5].x + r[6].x + r[7].x) * 0.25f;
        m1.y = (r[4].y + r[5].y + r[6].y + r[7].y) * 0.25f;
        m1.z = (r[4].z + r[5].z + r[6].z + r[7].z) * 0.25f;
        m1.w = (r[4].w + r[5].w + r[6].w + r[7].w) * 0.25f;

        float4 cs4, sq4;
        cs4.x = m0.x + m1.x;  cs4.y = m0.y + m1.y;
        cs4.z = m0.z + m1.z;  cs4.w = m0.w + m1.w;
        sq4.x = fmaf(m0.x, m0.x, m1.x * m1.x);
        sq4.y = fmaf(m0.y, m0.y, m1.y * m1.y);
        sq4.z = fmaf(m0.z, m0.z, m1.z * m1.z);
        sq4.w = fmaf(m0.w, m0.w, m1.w * m1.w);

        const int cur  = sl;
        const int nxt  = sl + NBLK;
        const bool more = (nxt < NSL);

        if (more) {   // issue next slice's loads NOW; they fly across the reduction
            const int b = nxt >> 5, pg = nxt & 31;
            const size_t base = ((size_t)b * Cn + cbase) * 256 + pg * 8 + f4;
#pragma unroll
            for (int t = 0; t < 4; ++t) {
                r[t]     = __ldg(X + base + (size_t)t * tstr);
                r[4 + t] = __ldg(X + base + 256 + (size_t)t * tstr);
            }
        }

        // reduce over the 4 cpair-threads sharing this f4 within the warp
#pragma unroll
        for (int off = 8; off <= 16; off <<= 1) {
            cs4.x += __shfl_xor_sync(0xFFFFFFFFu, cs4.x, off);
            cs4.y += __shfl_xor_sync(0xFFFFFFFFu, cs4.y, off);
            cs4.z += __shfl_xor_sync(0xFFFFFFFFu, cs4.z, off);
            cs4.w += __shfl_xor_sync(0xFFFFFFFFu, cs4.w, off);
            sq4.x += __shfl_xor_sync(0xFFFFFFFFu, sq4.x, off);
            sq4.y += __shfl_xor_sync(0xFFFFFFFFu, sq4.y, off);
            sq4.z += __shfl_xor_sync(0xFFFFFFFFu, sq4.z, off);
            sq4.w += __shfl_xor_sync(0xFFFFFFFFu, sq4.w, off);
        }
        if (l < 8) { scs[w][l] = cs4; ssq[w][l] = sq4; }
        __syncthreads();

        if (tid < 16) {                       // sum the 32 warp partials
            const int sel = tid >> 3, ff = tid & 7;
            float4 acc = make_float4(0.f, 0.f, 0.f, 0.f);
#pragma unroll
            for (int ww = 0; ww < 32; ++ww)
                acc = f4add(acc, sel ? ssq[ww][ff] : scs[ww][ff]);
            const int b = cur >> 5, pg = cur & 31;
            float4* gc4 = (float4*)g_comb;
            gc4[(size_t)sel * (Bn * Pn / 4) + b * 256 + pg * 8 + ff] = acc;
        }

        if (!more) break;
        __syncthreads();      // protect smem reuse next iteration
        sl = nxt;
    }

    // ---- publish once, count once per owned slice ----
    if (tid < 16) __threadfence();            // storers release ALL their g_comb writes
    if (tid == 0) s_nfin = 0;
    __syncthreads();                          // fences done before tid0 counts
    if (tid == 0) {
        int nf = 0;
        for (int s = blockIdx.x; s < NSL; s += NBLK) {
            const int b = s >> 5;
            if (atomicAdd(&g_done[b], 1) == Bn - 1)   // 32nd slice of batch b
                s_fin[nf++] = b;              // this block owns batch b's finale
        }
        s_nfin = nf;
    }
    __syncthreads();

    const int nfin = s_nfin;
    if (nfin == 0) return;
    __threadfence();                          // acquire: see other blocks' g_comb

    // ---- finales: box filter + cosine collapse + softmax per owned batch ----
    __shared__ float s_cs[34 * 34];
    __shared__ float red[32];
    __shared__ float bc[2];

    const int h    = tid >> 5;
    const int ww2  = tid & 31;
    const int lane = tid & 31;
    const int wid  = tid >> 5;

    for (int i = 0; i < nfin; ++i) {
        const int b = s_fin[i];
        if (tid == 0) atomicExch(&g_done[b], 0);   // reset for next launch

        const float cs = g_comb[(size_t)b * Pn + tid];
        const float sq = g_comb[(size_t)(Bn + b) * Pn + tid];
        const int mraw = __ldg(&mask[(size_t)b * Pn + tid]);

        for (int j = tid; j < 34 * 34; j += 1024) s_cs[j] = 0.f;
        __syncthreads();
        s_cs[(h + 1) * 34 + (ww2 + 1)] = cs;
        __syncthreads();

        float box = 0.f;
#pragma unroll
        for (int dh = 0; dh < 3; ++dh)
#pragma unroll
            for (int dw = 0; dw < 3; ++dw)
                box += s_cs[(h + dh) * 34 + (ww2 + dw)];

        const float lm  = box * (1.f / 9.f);
        const float nx  = sqrtf(sq);
        const float ny  = 16.f * fabsf(lm);       // sqrt(C)=16
        const float sim = (lm * cs) / (fmaxf(nx, 1e-6f) * fmaxf(ny, 1e-6f));
        const float score = mraw ? -INFINITY : -sim;

        float m = score;
#pragma unroll
        for (int o = 16; o; o >>= 1) m = fmaxf(m, __shfl_xor_sync(0xFFFFFFFFu, m, o));
        if (lane == 0) red[wid] = m;
        __syncthreads();
        if (wid == 0) {
            float v = red[lane];
#pragma unroll
            for (int o = 16; o; o >>= 1) v = fmaxf(v, __shfl_xor_sync(0xFFFFFFFFu, v, o));
            if (lane == 0) bc[0] = v;
        }
        __syncthreads();
        const float gmax = bc[0];

        const float e = __expf(score - gmax);
        float s = e;
#pragma unroll
        for (int o = 16; o; o >>= 1) s += __shfl_xor_sync(0xFFFFFFFFu, s, o);
        if (lane == 0) red[wid] = s;
        __syncthreads();
        if (wid == 0) {
            float v = red[lane];
#pragma unroll
            for (int o = 16; o; o >>= 1) v += __shfl_xor_sync(0xFFFFFFFFu, v, o);
            if (lane == 0) bc[1] = v;
        }
        __syncthreads();

        out[(size_t)b * Pn + tid] = e * __frcp_rn(bc[1]);
        __syncthreads();                      // s_cs/red/bc reuse across finales
    }
}

// ---------------------------------------------------------------------------
extern "C" void kernel_launch(void* const* d_in, const int* in_sizes, int n_in,
                              void* d_out, int out_size) {
    const float* x = (const float*)d_in[0];
    const int* mask = (const int*)d_in[1];
    float* out = (float*)d_out;

    fused_kernel<<<NBLK, 1024>>>(x, mask, out);
}

// round 11
// speedup vs baseline: 1.3509x; 1.3509x over previous
#include <cuda_runtime.h>
#include <math.h>

// Problem shape (fixed): x [T=4, B=32, C=256, H=32, W=32]
#define Tn 4
#define Bn 32
#define Cn 256
#define Pn 1024
#define NSL 2048            // slices = B * 64 pixel-groups (16 pixels each, all channels)
#define NBLK 296            // persistent grid = two CTAs per SM

// Per-pixel sums: [sel][b][p], sel 0 = csum, 1 = ssq. 256 KB, L2-resident.
__device__ float g_comb[2 * Bn * Pn];

__device__ __forceinline__ float4 f4add(float4 a, float4 b) {
    return make_float4(a.x + b.x, a.y + b.y, a.z + b.z, a.w + b.w);
}

// ---------------------------------------------------------------------------
// Persistent reduce, 512-thread CTAs (2 per SM for barrier-decoupled issue).
// Slice = (b, pg): 16 pixels (4 float4) x 256 channels x 4 t.
//   warp w (0..15) covers channels [16w, 16w+16);
//   lane l: f4 = l&3 (pixel quad), cpair = l>>2 -> channels 16w+2*(l>>2), +1.
// Per slice per thread: 8 x LDG.128 (2 channels x 4 t), next slice prefetched
// across the reduction. Shuffle over cpair (x8), smem over 16 warps, tid<8
// write the final per-pixel cs/sq float4s to g_comb.
// ---------------------------------------------------------------------------
__global__ void __launch_bounds__(512, 2) reduce_kernel(const float* __restrict__ xf) {
    const float4* __restrict__ X = (const float4*)xf;
    const int tid   = threadIdx.x;
    const int w     = tid >> 5;            // 0..15
    const int l     = tid & 31;
    const int f4    = l & 3;               // pixel quad within the 16-pixel group
    const int cbase = w * 16 + (l >> 2) * 2;

    __shared__ float4 scs[16][4];
    __shared__ float4 ssq[16][4];

    const size_t tstr = (size_t)Bn * Cn * 256;   // t-plane stride in float4

    int sl = blockIdx.x;
    float4 r[8];
    {
        const int b = sl >> 6, pg = sl & 63;
        const size_t base = ((size_t)b * Cn + cbase) * 256 + pg * 4 + f4;
#pragma unroll
        for (int t = 0; t < 4; ++t) {
            r[t]     = __ldg(X + base + (size_t)t * tstr);
            r[4 + t] = __ldg(X + base + 256 + (size_t)t * tstr);
        }
    }

    for (;;) {
        float4 m0, m1;
        m0.x = (r[0].x + r[1].x + r[2].x + r[3].x) * 0.25f;
        m0.y = (r[0].y + r[1].y + r[2].y + r[3].y) * 0.25f;
        m0.z = (r[0].z + r[1].z + r[2].z + r[3].z) * 0.25f;
        m0.w = (r[0].w + r[1].w + r[2].w + r[3].w) * 0.25f;
        m1.x = (r[4].x + r[5].x + r[6].x + r[7].x) * 0.25f;
        m1.y = (r[4].y + r[5].y + r[6].y + r[7].y) * 0.25f;
        m1.z = (r[4].z + r[5].z + r[6].z + r[7].z) * 0.25f;
        m1.w = (r[4].w + r[5].w + r[6].w + r[7].w) * 0.25f;

        float4 cs4, sq4;
        cs4.x = m0.x + m1.x;  cs4.y = m0.y + m1.y;
        cs4.z = m0.z + m1.z;  cs4.w = m0.w + m1.w;
        sq4.x = fmaf(m0.x, m0.x, m1.x * m1.x);
        sq4.y = fmaf(m0.y, m0.y, m1.y * m1.y);
        sq4.z = fmaf(m0.z, m0.z, m1.z * m1.z);
        sq4.w = fmaf(m0.w, m0.w, m1.w * m1.w);

        const int cur  = sl;
        const int nxt  = sl + NBLK;
        const bool more = (nxt < NSL);

        if (more) {   // issue next slice's loads NOW; they fly across the reduction
            const int b = nxt >> 6, pg = nxt & 63;
            const size_t base = ((size_t)b * Cn + cbase) * 256 + pg * 4 + f4;
#pragma unroll
            for (int t = 0; t < 4; ++t) {
                r[t]     = __ldg(X + base + (size_t)t * tstr);
                r[4 + t] = __ldg(X + base + 256 + (size_t)t * tstr);
            }
        }

        // reduce over the 8 cpair-threads sharing this f4 within the warp
#pragma unroll
        for (int off = 4; off <= 16; off <<= 1) {
            cs4.x += __shfl_xor_sync(0xFFFFFFFFu, cs4.x, off);
            cs4.y += __shfl_xor_sync(0xFFFFFFFFu, cs4.y, off);
            cs4.z += __shfl_xor_sync(0xFFFFFFFFu, cs4.z, off);
            cs4.w += __shfl_xor_sync(0xFFFFFFFFu, cs4.w, off);
            sq4.x += __shfl_xor_sync(0xFFFFFFFFu, sq4.x, off);
            sq4.y += __shfl_xor_sync(0xFFFFFFFFu, sq4.y, off);
            sq4.z += __shfl_xor_sync(0xFFFFFFFFu, sq4.z, off);
            sq4.w += __shfl_xor_sync(0xFFFFFFFFu, sq4.w, off);
        }
        if (l < 4) { scs[w][l] = cs4; ssq[w][l] = sq4; }
        __syncthreads();

        if (tid < 8) {                        // sum the 16 warp partials
            const int sel = tid >> 2, ff = tid & 3;
            float4 acc = make_float4(0.f, 0.f, 0.f, 0.f);
#pragma unroll
            for (int ww = 0; ww < 16; ++ww)
                acc = f4add(acc, sel ? ssq[ww][ff] : scs[ww][ff]);
            const int b = cur >> 6, pg = cur & 63;
            float4* gc4 = (float4*)g_comb;
            gc4[(size_t)sel * (Bn * Pn / 4) + b * 256 + pg * 4 + ff] = acc;
        }

        if (!more) break;
        __syncthreads();      // protect smem reuse next iteration
        sl = nxt;
    }
}

// ---------------------------------------------------------------------------
// Final: per batch — per-pixel cs/sq (256 KB in L2), 3x3 zero-padded box
// filter, cosine collapse, mask, softmax over 1024 pixels.
// ---------------------------------------------------------------------------
__global__ void __launch_bounds__(1024) final_kernel(const int* __restrict__ mask,
                                                     float* __restrict__ out) {
    const int b    = blockIdx.x;
    const int tid  = threadIdx.x;           // pixel index
    const int h    = tid >> 5;
    const int w    = tid & 31;
    const int lane = tid & 31;
    const int wid  = tid >> 5;

    const float cs = __ldg(&g_comb[(size_t)b * Pn + tid]);
    const float sq = __ldg(&g_comb[(size_t)(Bn + b) * Pn + tid]);
    const int mraw = __ldg(&mask[(size_t)b * Pn + tid]);

    // 3x3 zero-padded box sum over 32x32
    __shared__ float s_cs[34 * 34];
    for (int i = tid; i < 34 * 34; i += 1024) s_cs[i] = 0.f;
    __syncthreads();
    s_cs[(h + 1) * 34 + (w + 1)] = cs;
    __syncthreads();

    float box = 0.f;
#pragma unroll
    for (int dh = 0; dh < 3; ++dh)
#pragma unroll
        for (int dw = 0; dw < 3; ++dw)
            box += s_cs[(h + dh) * 34 + (w + dw)];

    const float lm  = box * (1.f / 9.f);
    const float nx  = sqrtf(sq);
    const float ny  = 16.f * fabsf(lm);       // sqrt(C)=16
    const float sim = (lm * cs) / (fmaxf(nx, 1e-6f) * fmaxf(ny, 1e-6f));
    const float score = mraw ? -INFINITY : -sim;

    // block softmax over 1024 entries
    __shared__ float red[32];
    __shared__ float bc[2];

    float m = score;
#pragma unroll
    for (int o = 16; o; o >>= 1) m = fmaxf(m, __shfl_xor_sync(0xFFFFFFFFu, m, o));
    if (lane == 0) red[wid] = m;
    __syncthreads();
    if (wid == 0) {
        float v = red[lane];
#pragma unroll
        for (int o = 16; o; o >>= 1) v = fmaxf(v, __shfl_xor_sync(0xFFFFFFFFu, v, o));
        if (lane == 0) bc[0] = v;
    }
    __syncthreads();
    const float gmax = bc[0];

    const float e = __expf(score - gmax);
    float s = e;
#pragma unroll
    for (int o = 16; o; o >>= 1) s += __shfl_xor_sync(0xFFFFFFFFu, s, o);
    if (lane == 0) red[wid] = s;
    __syncthreads();
    if (wid == 0) {
        float v = red[lane];
#pragma unroll
        for (int o = 16; o; o >>= 1) v += __shfl_xor_sync(0xFFFFFFFFu, v, o);
        if (lane == 0) bc[1] = v;
    }
    __syncthreads();

    out[(size_t)b * Pn + tid] = e * __frcp_rn(bc[1]);
}

// ---------------------------------------------------------------------------
extern "C" void kernel_launch(void* const* d_in, const int* in_sizes, int n_in,
                              void* d_out, int out_size) {
    const float* x = (const float*)d_in[0];
    const int* mask = (const int*)d_in[1];
    float* out = (float*)d_out;

    reduce_kernel<<<NBLK, 512>>>(x);
    final_kernel<<<Bn, 1024>>>(mask, out);
}

// round 13
// speedup vs baseline: 1.4376x; 1.0642x over previous
#include <cuda_runtime.h>
#include <math.h>

// Problem shape (fixed): x [T=4, B=32, C=256, H=32, W=32]
#define Tn 4
#define Bn 32
#define Cn 256
#define Pn 1024
#define NSL 1024            // slices = B * 32 pixel-groups (32 pixels each, all channels)
#define NBLK 148            // persistent grid = one CTA per SM

// Per-pixel sums: [sel][b][p], sel 0 = csum, 1 = ssq. 256 KB, L2-resident.
__device__ float g_comb[2 * Bn * Pn];

// ---------------------------------------------------------------------------
// Persistent reduce (R6 slice mapping). Slice = (b, pg): 32 pixels x 256
// channels x 4 t. warp w: channels [8w,8w+8); lane l: f4=l&7, cpair=l>>3.
// 8 x LDG.128 per thread/slice; next slice prefetched across the reduction.
// NEW: scalar transposed combine (all 32 warps, conflict-free via pad-33) and
// parity double-buffered smem -> ONE barrier per slice.
// ---------------------------------------------------------------------------
__global__ void __launch_bounds__(1024, 1) reduce_kernel(const float* __restrict__ xf) {
    const float4* __restrict__ X = (const float4*)xf;
    const int tid   = threadIdx.x;
    const int w     = tid >> 5;            // 0..31
    const int l     = tid & 31;
    const int f4    = l & 7;
    const int cbase = w * 8 + (l >> 3) * 2;

    // [parity][warp][33] scalars; pad 33 makes column reads conflict-free.
    __shared__ float scs[2][32][33];
    __shared__ float ssq[2][32][33];

    const size_t tstr = (size_t)Bn * Cn * 256;   // t-plane stride in float4

    int sl  = blockIdx.x;
    int par = 0;
    float4 r[8];
    {
        const int b = sl >> 5, pg = sl & 31;
        const size_t base = ((size_t)b * Cn + cbase) * 256 + pg * 8 + f4;
#pragma unroll
        for (int t = 0; t < 4; ++t) {
            r[t]     = __ldg(X + base + (size_t)t * tstr);
            r[4 + t] = __ldg(X + base + 256 + (size_t)t * tstr);
        }
    }

    for (;;) {
        float4 m0, m1;
        m0.x = (r[0].x + r[1].x + r[2].x + r[3].x) * 0.25f;
        m0.y = (r[0].y + r[1].y + r[2].y + r[3].y) * 0.25f;
        m0.z = (r[0].z + r[1].z + r[2].z + r[3].z) * 0.25f;
        m0.w = (r[0].w + r[1].w + r[2].w + r[3].w) * 0.25f;
        m1.x = (r[4].x + r[5].x + r[6].x + r[7].x) * 0.25f;
        m1.y = (r[4].y + r[5].y + r[6].y + r[7].y) * 0.25f;
        m1.z = (r[4].z + r[5].z + r[6].z + r[7].z) * 0.25f;
        m1.w = (r[4].w + r[5].w + r[6].w + r[7].w) * 0.25f;

        float4 cs4, sq4;
        cs4.x = m0.x + m1.x;  cs4.y = m0.y + m1.y;
        cs4.z = m0.z + m1.z;  cs4.w = m0.w + m1.w;
        sq4.x = fmaf(m0.x, m0.x, m1.x * m1.x);
        sq4.y = fmaf(m0.y, m0.y, m1.y * m1.y);
        sq4.z = fmaf(m0.z, m0.z, m1.z * m1.z);
        sq4.w = fmaf(m0.w, m0.w, m1.w * m1.w);

        const int cur  = sl;
        const int nxt  = sl + NBLK;
        const bool more = (nxt < NSL);

        if (more) {   // issue next slice's loads NOW; they fly across the reduction
            const int b = nxt >> 5, pg = nxt & 31;
            const size_t base = ((size_t)b * Cn + cbase) * 256 + pg * 8 + f4;
#pragma unroll
            for (int t = 0; t < 4; ++t) {
                r[t]     = __ldg(X + base + (size_t)t * tstr);
                r[4 + t] = __ldg(X + base + 256 + (size_t)t * tstr);
            }
        }

        // reduce over the 4 cpair-threads sharing this f4 within the warp
#pragma unroll
        for (int off = 8; off <= 16; off <<= 1) {
            cs4.x += __shfl_xor_sync(0xFFFFFFFFu, cs4.x, off);
            cs4.y += __shfl_xor_sync(0xFFFFFFFFu, cs4.y, off);
            cs4.z += __shfl_xor_sync(0xFFFFFFFFu, cs4.z, off);
            cs4.w += __shfl_xor_sync(0xFFFFFFFFu, cs4.w, off);
            sq4.x += __shfl_xor_sync(0xFFFFFFFFu, sq4.x, off);
            sq4.y += __shfl_xor_sync(0xFFFFFFFFu, sq4.y, off);
            sq4.z += __shfl_xor_sync(0xFFFFFFFFu, sq4.z, off);
            sq4.w += __shfl_xor_sync(0xFFFFFFFFu, sq4.w, off);
        }
        // lanes 0..7 hold this warp's partials for ff=l: store as scalars j=4l..4l+3
        if (l < 8) {
            scs[par][w][l * 4 + 0] = cs4.x;
            scs[par][w][l * 4 + 1] = cs4.y;
            scs[par][w][l * 4 + 2] = cs4.z;
            scs[par][w][l * 4 + 3] = cs4.w;
            ssq[par][w][l * 4 + 0] = sq4.x;
            ssq[par][w][l * 4 + 1] = sq4.y;
            ssq[par][w][l * 4 + 2] = sq4.z;
            ssq[par][w][l * 4 + 3] = sq4.w;
        }
        __syncthreads();      // the ONLY barrier per slice (parity double-buffer)

        // transposed combine: warp w reduces scalar j=w across all 32 warps.
        // column read scs[par][l][w]: bank = (33*l + w) % 32 = (l + w) % 32 -> conflict-free
        {
            float vc = scs[par][l][w];
            float vq = ssq[par][l][w];
#pragma unroll
            for (int off = 16; off; off >>= 1) {
                vc += __shfl_xor_sync(0xFFFFFFFFu, vc, off);
                vq += __shfl_xor_sync(0xFFFFFFFFu, vq, off);
            }
            if (l == 0) {
                const int b = cur >> 5, pg = cur & 31;
                const int o = b * 1024 + pg * 32 + w;   // scalar j=w of this slice
                g_comb[o] = vc;
                g_comb[Bn * Pn + o] = vq;
            }
        }

        if (!more) break;
        par ^= 1;
        sl = nxt;
    }
}

// ---------------------------------------------------------------------------
// Final: per batch — per-pixel cs/sq (256 KB in L2), 3x3 zero-padded box
// filter, cosine collapse, mask, softmax over 1024 pixels.
// ---------------------------------------------------------------------------
__global__ void __launch_bounds__(1024) final_kernel(const int* __restrict__ mask,
                                                     float* __restrict__ out) {
    const int b    = blockIdx.x;
    const int tid  = threadIdx.x;           // pixel index
    const int h    = tid >> 5;
    const int w    = tid & 31;
    const int lane = tid & 31;
    const int wid  = tid >> 5;

    const float cs = __ldg(&g_comb[(size_t)b * Pn + tid]);
    const float sq = __ldg(&g_comb[(size_t)(Bn + b) * Pn + tid]);
    const int mraw = __ldg(&mask[(size_t)b * Pn + tid]);

    // 3x3 zero-padded box sum over 32x32
    __shared__ float s_cs[34 * 34];
    for (int i = tid; i < 34 * 34; i += 1024) s_cs[i] = 0.f;
    __syncthreads();
    s_cs[(h + 1) * 34 + (w + 1)] = cs;
    __syncthreads();

    float box = 0.f;
#pragma unroll
    for (int dh = 0; dh < 3; ++dh)
#pragma unroll
        for (int dw = 0; dw < 3; ++dw)
            box += s_cs[(h + dh) * 34 + (w + dw)];

    const float lm  = box * (1.f / 9.f);
    const float nx  = sqrtf(sq);
    const float ny  = 16.f * fabsf(lm);       // sqrt(C)=16
    const float sim = (lm * cs) / (fmaxf(nx, 1e-6f) * fmaxf(ny, 1e-6f));
    const float score = mraw ? -INFINITY : -sim;

    // block softmax over 1024 entries
    __shared__ float red[32];
    __shared__ float bc[2];

    float m = score;
#pragma unroll
    for (int o = 16; o; o >>= 1) m = fmaxf(m, __shfl_xor_sync(0xFFFFFFFFu, m, o));
    if (lane == 0) red[wid] = m;
    __syncthreads();
    if (wid == 0) {
        float v = red[lane];
#pragma unroll
        for (int o = 16; o; o >>= 1) v = fmaxf(v, __shfl_xor_sync(0xFFFFFFFFu, v, o));
        if (lane == 0) bc[0] = v;
    }
    __syncthreads();
    const float gmax = bc[0];

    const float e = __expf(score - gmax);
    float s = e;
#pragma unroll
    for (int o = 16; o; o >>= 1) s += __shfl_xor_sync(0xFFFFFFFFu, s, o);
    if (lane == 0) red[wid] = s;
    __syncthreads();
    if (wid == 0) {
        float v = red[lane];
#pragma unroll
        for (int o = 16; o; o >>= 1) v += __shfl_xor_sync(0xFFFFFFFFu, v, o);
        if (lane == 0) bc[1] = v;
    }
    __syncthreads();

    out[(size_t)b * Pn + tid] = e * __frcp_rn(bc[1]);
}

// ---------------------------------------------------------------------------
extern "C" void kernel_launch(void* const* d_in, const int* in_sizes, int n_in,
                              void* d_out, int out_size) {
    const float* x = (const float*)d_in[0];
    const int* mask = (const int*)d_in[1];
    float* out = (float*)d_out;

    reduce_kernel<<<NBLK, 1024>>>(x);
    final_kernel<<<Bn, 1024>>>(mask, out);
}